// round 2
// baseline (speedup 1.0000x reference)
#include <cuda_runtime.h>
#include <math_constants.h>

// VQ-VAE vector quantizer. Bitwise-emulates the reference fp32 pipeline:
//   d_k = fl32( fl32(A - 2*M_k) + B_k )
//   A   = sum(x^2)  (XLA GPU row-reduce order: float2 leaves + shfl tree)
//   M_k = x . e_k   (sequential ascending-d fp32 FMA chain from 0 = cublas simt)
//   B_k = sum(e^2)  (sequential; error ~1e-12, irrelevant at ulp(64)=7.6e-6)
//   argmin with tie -> lowest index.
//
// Inputs:  d_in[0] = inputs [64, 64, 32, 32] f32 (NCHW, C=D=64)
//          d_in[1] = embedding [1024, 64] f32
// Output (f32): quantized_st [64,64,32,32], encodings [64,32,32], loss, nll

#define K_CODES   1024
#define D_DIM     64
#define TP        128     // positions per block
#define TK        128     // codes per chunk
#define ES_STRIDE 132     // padded code-stride for transposed E tile
#define ENC_OFF   4194304
#define LOSS_OFF  4259840
#define NLL_OFF   4259841
#define TOTAL_OUT 4259842

__device__ double g_loss_acc;
__device__ float  g_eB[K_CODES];   // fp32 ||e_k||^2, sequential chain

// ---- packed f32x2 helpers (sm_100+); each lane rounds like scalar FFMA ----
__device__ __forceinline__ unsigned long long pk2(float a, float b) {
    unsigned long long r;
    asm("mov.b64 %0, {%1, %2};" : "=l"(r) : "f"(a), "f"(b));
    return r;
}
__device__ __forceinline__ void upk2(unsigned long long v, float& a, float& b) {
    asm("mov.b64 {%0, %1}, %2;" : "=f"(a), "=f"(b) : "l"(v));
}
__device__ __forceinline__ unsigned long long ffma2(unsigned long long a,
                                                    unsigned long long b,
                                                    unsigned long long c) {
    unsigned long long r;
    asm("fma.rn.f32x2 %0, %1, %2, %3;" : "=l"(r) : "l"(a), "l"(b), "l"(c));
    return r;
}

// Kernel 0: B_k = fp32 sequential fma chain of e^2; zero loss accumulator.
__global__ void vq_prep(const float* __restrict__ emb) {
    int k = blockIdx.x * blockDim.x + threadIdx.x;
    if (k == 0) g_loss_acc = 0.0;
    if (k < K_CODES) {
        const float* row = emb + k * D_DIM;
        float b = 0.0f;
        #pragma unroll
        for (int i = 0; i < D_DIM; i++) b = __fmaf_rn(row[i], row[i], b);
        g_eB[k] = b;
    }
}

// Main kernel: one block = 128 positions of one image, all 1024 codes.
__global__ void __launch_bounds__(256) vq_main(const float* __restrict__ x,
                                               const float* __restrict__ emb,
                                               float* __restrict__ out,
                                               int out_size) {
    extern __shared__ float smem[];
    float* Xs   = smem;                 // [64][128]  = 8192 floats
    float* Es   = smem + 8192;          // [64][132]  = 8448 floats (d-major)
    float* Bs   = Es + 64 * ES_STRIDE;  // [128]  ||e||^2 chunk
    float* As   = Bs + TK;              // [128]  ||x||^2 per position
    int*   idx_s = (int*)(As + TP);     // [128]
    // reduction overlays Es (only used after last chunk's compute):
    float* rV = Es;                     // [16][128]
    int*   rI = (int*)(Es + 2048);      // [16][128]

    const int tid = threadIdx.x;
    const int tx = tid & 15;            // position group 0..15
    const int ty = tid >> 4;            // code group 0..15
    const int b  = blockIdx.x >> 3;
    const int p0 = (blockIdx.x & 7) * TP;

    // ---- load X tile: Xs[d][pp] = x[(b*64+d)*1024 + p0 + pp] ----
    {
        const float* xb = x + (size_t)b * 65536 + p0;
        int lane = tid & 31;
        int r0 = tid >> 5;
        #pragma unroll
        for (int it = 0; it < 8; it++) {
            int d = r0 + it * 8;
            float4 v = *(const float4*)(xb + d * 1024 + lane * 4);
            *(float4*)&Xs[d * TP + lane * 4] = v;
        }
    }
    __syncthreads();

    // ---- A_p = sum(x^2), XLA GPU row-reduce emulation:
    //      float2 leaf l_t = fma(x[2t+1], x[2t+1], fl(x[2t]*x[2t])),
    //      then shfl-down tree offsets 16,8,4,2,1 (value at lane 0). ----
    if (tid < TP) {
        float l[32];
        #pragma unroll
        for (int t = 0; t < 32; t++) {
            float a = Xs[(2 * t) * TP + tid];
            float c = Xs[(2 * t + 1) * TP + tid];
            l[t] = __fmaf_rn(c, c, __fmul_rn(a, a));
        }
        #pragma unroll
        for (int off = 16; off >= 1; off >>= 1)
            #pragma unroll
            for (int t = 0; t < 16; t++)
                if (t < off) l[t] = __fadd_rn(l[t], l[t + off]);
        As[tid] = l[0];
    }

    float bv[8];
    int   bi[8];
    #pragma unroll
    for (int i = 0; i < 8; i++) { bv[i] = CUDART_INF_F; bi[i] = 0; }

    // ---- K chunks ----
    for (int kc = 0; kc < K_CODES / TK; kc++) {
        const int k0 = kc * TK;
        __syncthreads();   // As ready (first iter) / previous compute done

        // load E chunk transposed: Es[d][k] = emb[(k0+k)*64 + d]
        {
            int dchunk = tid & 15;
            int krow   = tid >> 4;
            #pragma unroll
            for (int it = 0; it < 8; it++) {
                int k = krow + it * 16;
                float4 v = *(const float4*)(emb + (size_t)(k0 + k) * 64 + dchunk * 4);
                Es[(dchunk * 4 + 0) * ES_STRIDE + k] = v.x;
                Es[(dchunk * 4 + 1) * ES_STRIDE + k] = v.y;
                Es[(dchunk * 4 + 2) * ES_STRIDE + k] = v.z;
                Es[(dchunk * 4 + 3) * ES_STRIDE + k] = v.w;
            }
            if (tid < TK) Bs[tid] = g_eB[k0 + tid];
        }
        __syncthreads();

        // dot accumulators: 4 position-pairs x 8 codes, init 0
        // (sequential ascending-d fp32 FMA chain per lane = cublas simt order)
        unsigned long long acc[4][8];
        #pragma unroll
        for (int k = 0; k < 8; k++)
            #pragma unroll
            for (int p2 = 0; p2 < 4; p2++) acc[p2][k] = 0ull;

        #pragma unroll 8
        for (int d = 0; d < D_DIM; d++) {
            float4 xa  = *(const float4*)&Xs[d * TP + tx * 8];
            float4 xb4 = *(const float4*)&Xs[d * TP + tx * 8 + 4];
            float4 ea  = *(const float4*)&Es[d * ES_STRIDE + ty * 8];
            float4 eb  = *(const float4*)&Es[d * ES_STRIDE + ty * 8 + 4];
            unsigned long long x2[4] = { pk2(xa.x, xa.y),  pk2(xa.z, xa.w),
                                         pk2(xb4.x, xb4.y), pk2(xb4.z, xb4.w) };
            float ev[8] = { ea.x, ea.y, ea.z, ea.w, eb.x, eb.y, eb.z, eb.w };
            #pragma unroll
            for (int k = 0; k < 8; k++) {
                unsigned long long ed = pk2(ev[k], ev[k]);
                #pragma unroll
                for (int p2 = 0; p2 < 4; p2++)
                    acc[p2][k] = ffma2(x2[p2], ed, acc[p2][k]);
            }
        }

        // fold: d = fl(fl(A - 2M) + B); strict < keeps lowest index (ascending k)
        #pragma unroll
        for (int p2 = 0; p2 < 4; p2++) {
            float A0 = As[tx * 8 + 2 * p2];
            float A1 = As[tx * 8 + 2 * p2 + 1];
            int p = 2 * p2;
            #pragma unroll
            for (int k = 0; k < 8; k++) {
                float M0, M1;
                upk2(acc[p2][k], M0, M1);
                float Bk = Bs[ty * 8 + k];
                int kk = k0 + ty * 8 + k;
                float d0 = __fadd_rn(__fmaf_rn(-2.0f, M0, A0), Bk);
                float d1 = __fadd_rn(__fmaf_rn(-2.0f, M1, A1), Bk);
                if (d0 < bv[p])     { bv[p] = d0;     bi[p] = kk; }
                if (d1 < bv[p + 1]) { bv[p + 1] = d1; bi[p + 1] = kk; }
            }
        }
    }

    // ---- cross-thread (ty) reduction per position: min, tie -> lowest idx ----
    __syncthreads();
    #pragma unroll
    for (int i = 0; i < 8; i++) {
        int p = tx * 8 + i;
        rV[ty * TP + p] = bv[i];
        rI[ty * TP + p] = bi[i];
    }
    __syncthreads();
    if (tid < TP) {
        float best = rV[tid];
        int besti  = rI[tid];
        #pragma unroll
        for (int t = 1; t < 16; t++) {
            float v = rV[t * TP + tid];
            int iv  = rI[t * TP + tid];
            if (v < best || (v == best && iv < besti)) { best = v; besti = iv; }
        }
        idx_s[tid] = besti;
        if (out_size >= TOTAL_OUT)
            out[ENC_OFF + b * 1024 + p0 + tid] = (float)besti;
    }
    __syncthreads();

    // ---- output (straight-through: x + (q - x)) + loss partial ----
    float lsum = 0.0f;
    #pragma unroll
    for (int j = 0; j < 32; j++) {
        int i  = tid + j * 256;
        int pp = i & 127;
        int d  = i >> 7;
        float q  = emb[(size_t)idx_s[pp] * 64 + d];
        float xv = Xs[d * TP + pp];
        float df = __fadd_rn(q, -xv);
        lsum += df * df;
        out[((size_t)b * 64 + d) * 1024 + p0 + pp] = __fadd_rn(xv, df);
    }
    #pragma unroll
    for (int off = 16; off > 0; off >>= 1)
        lsum += __shfl_down_sync(0xffffffffu, lsum, off);
    __shared__ float wsum[8];
    if ((tid & 31) == 0) wsum[tid >> 5] = lsum;
    __syncthreads();
    if (tid == 0) {
        float t = 0.0f;
        #pragma unroll
        for (int w = 0; w < 8; w++) t += wsum[w];
        atomicAdd(&g_loss_acc, (double)t);
    }
}

// Tail kernel: finalize loss + nll.
__global__ void vq_final(float* __restrict__ out, int out_size) {
    if (out_size >= TOTAL_OUT) {
        float m = (float)(g_loss_acc * (1.0 / 4194304.0));
        out[LOSS_OFF] = __fadd_rn(m, __fmul_rn(0.25f, m));
        out[NLL_OFF]  = 1.0f;
    }
}

extern "C" void kernel_launch(void* const* d_in, const int* in_sizes, int n_in,
                              void* d_out, int out_size) {
    const float* x   = (const float*)d_in[0];
    const float* emb = (const float*)d_in[1];
    if (n_in >= 2 && in_sizes[0] == K_CODES * D_DIM) {
        const float* t = x; x = emb; emb = t;
    }
    float* out = (float*)d_out;

    const int smem_bytes = (8192 + 64 * ES_STRIDE + TK + TP) * 4 + TP * 4; // 68096
    cudaFuncSetAttribute(vq_main, cudaFuncAttributeMaxDynamicSharedMemorySize,
                         smem_bytes);

    vq_prep<<<4, 256>>>(emb);
    vq_main<<<512, 256, smem_bytes>>>(x, emb, out, out_size);
    vq_final<<<1, 1>>>(out, out_size);
}